// round 14
// baseline (speedup 1.0000x reference)
#include <cuda_runtime.h>
#include <cuda_fp16.h>
#include <cstdint>

#define N_NODES 16384
#define N_EDGES 32768
#define D 128
#define EDGE_DIM 10
#define EH 32
#define NCOLS (EH * D + D + D)   // 4096 (L) + 128 (l2 bias) + 128 (root) = 4352
#define KS 128                   // fp16 single-term: A=hi, B=hi (K=128)
#define BM 128
#define BN 128
#define STAGE_BYTES (BM * 128 + BN * 128)   // 32 KB per stage

// ---------------- scratch (static device globals; no allocation) ----------------
__device__ __half g_Y[N_NODES * NCOLS];    // 142 MB (fp16 Y)
__device__ __half g_A3[N_NODES * KS];
__device__ __half g_B31[NCOLS * KS];
__device__ __half g_B32[NCOLS * KS];
__device__ float g_h1[N_EDGES * EH];
__device__ float g_h2[N_EDGES * EH];
__device__ float g_acc[N_NODES * D];       // zero-init; every combine restores zero
__device__ float g_cnt[N_NODES];
__device__ int   g_idx[2 * N_EDGES];
__device__ int   g_is64;
// edge sort-by-src
__device__ int g_srcCount[N_NODES];
__device__ int g_srcOff[N_NODES];
__device__ int g_rank[N_EDGES];
__device__ int g_perm[N_EDGES];

__device__ __forceinline__ uint32_t smem_u32(const void* p) {
    uint32_t a;
    asm("{ .reg .u64 t; cvta.to.shared.u64 t, %1; cvt.u32.u64 %0, t; }" : "=r"(a) : "l"(p));
    return a;
}
#define CP_ASYNC16(saddr, gptr) \
    asm volatile("cp.async.cg.shared.global [%0], [%1], 16;" :: "r"(saddr), "l"(gptr))
#define CP_COMMIT() asm volatile("cp.async.commit_group;" ::: "memory")
#define CP_WAITG(n) asm volatile("cp.async.wait_group %0;" :: "n"(n) : "memory")

// ---------------- edge_index dtype detection + zero counters ----------------
__global__ void detect_zero(const long long* __restrict__ ei) {
    int i = blockIdx.x * blockDim.x + threadIdx.x;
    if (i < N_NODES) { g_srcCount[i] = 0; g_cnt[i] = 0.f; }
    if (i == 0) {
        int ok = 1;
        for (int k = 0; k < 128; k++) {
            long long v = ei[k];
            if (v < 0 || v >= N_NODES) { ok = 0; break; }
        }
        g_is64 = ok;
    }
}

// ---------------- convert indices + count (fused) ----------------
__global__ void conv_count(const void* __restrict__ ei) {
    int e = blockIdx.x * blockDim.x + threadIdx.x;
    if (e >= N_EDGES) return;
    long long vs, vd;
    if (g_is64) {
        vs = ((const long long*)ei)[e];
        vd = ((const long long*)ei)[N_EDGES + e];
    } else {
        vs = ((const int*)ei)[e];
        vd = ((const int*)ei)[N_EDGES + e];
    }
    int s = (int)vs, d = (int)vd;
    s = s < 0 ? 0 : (s >= N_NODES ? N_NODES - 1 : s);
    d = d < 0 ? 0 : (d >= N_NODES ? N_NODES - 1 : d);
    g_idx[e] = s;
    g_idx[N_EDGES + e] = d;
    g_rank[e] = atomicAdd(&g_srcCount[s], 1);
    atomicAdd(&g_cnt[d], 1.0f);
}

__global__ void scan_counts() {          // 1 block, 1024 threads, 16 elems each
    __shared__ int part[1024];
    int t = threadIdx.x;
    int base = t * 16;
    int local[16];
    int s = 0;
#pragma unroll
    for (int i = 0; i < 16; i++) { local[i] = s; s += g_srcCount[base + i]; }
    part[t] = s;
    __syncthreads();
    for (int off = 1; off < 1024; off <<= 1) {
        int v = (t >= off) ? part[t - off] : 0;
        __syncthreads();
        part[t] += v;
        __syncthreads();
    }
    int pre = (t == 0) ? 0 : part[t - 1];
#pragma unroll
    for (int i = 0; i < 16; i++) g_srcOff[base + i] = pre + local[i];
}

// ---------------- h = relu(edge_attr @ l1w + l1b) both sets + place_edges (fused) ----------------
__global__ void build_h2(const float* __restrict__ ea,
                         const float* __restrict__ wA, const float* __restrict__ bA,
                         const float* __restrict__ wB, const float* __restrict__ bB,
                         float* __restrict__ hA, float* __restrict__ hB) {
    int idx = blockIdx.x * blockDim.x + threadIdx.x;
    if (idx >= N_EDGES * EH) return;
    int e = idx >> 5, j = idx & 31;
    if (j == 0) g_perm[g_srcOff[g_idx[e]] + g_rank[e]] = e;   // place edge in sorted order
    const float* ear = ea + e * EDGE_DIM;
    float sA = bA[j], sB = bB[j];
#pragma unroll
    for (int d = 0; d < EDGE_DIM; d++) {
        float v = ear[d];
        sA = fmaf(v, wA[d * EH + j], sA);
        sB = fmaf(v, wB[d * EH + j], sB);
    }
    hA[idx] = fmaxf(sA, 0.f);
    hB[idx] = fmaxf(sB, 0.f);
}

// ---------------- fp16 conversion of A (layer-1 input only), half2 ----------------
__global__ void convA(const float* __restrict__ X, __half* __restrict__ A3) {
    int idx = blockIdx.x * blockDim.x + threadIdx.x;
    if (idx >= N_NODES * D / 2) return;
    float2 v = ((const float2*)X)[idx];
    ((__half2*)A3)[idx] = __floats2half2_rn(v.x, v.y);
}

// ---------------- both B' matrices in one kernel ----------------
__global__ void buildB2(const float* __restrict__ l2wA, const float* __restrict__ bA,
                        const float* __restrict__ rootA,
                        const float* __restrict__ l2wB, const float* __restrict__ bB,
                        const float* __restrict__ rootB,
                        __half* __restrict__ B3A, __half* __restrict__ B3B) {
    int idx = blockIdx.x * blockDim.x + threadIdx.x;   // n*128 + k
    if (idx >= NCOLS * D) return;
    int n = idx >> 7, k = idx & 127;
    float vA, vB;
    if (n < EH * D) {
        int pos = (n >> 7) * (D * D) + k * D + (n & 127);
        vA = l2wA[pos]; vB = l2wB[pos];
    } else if (n < EH * D + D) {
        int pos = k * D + (n - EH * D);
        vA = bA[pos]; vB = bB[pos];
    } else {
        int pos = k * D + (n - EH * D - D);
        vA = rootA[pos]; vB = rootB[pos];
    }
    B3A[idx] = __float2half_rn(vA);
    B3B[idx] = __float2half_rn(vB);
}

// ---------------- HMMA GEMM: K=128 fully prefetched, CTA 128x128, 4 warps of 64x64 ----------------
__global__ void __launch_bounds__(128) gemm_mma(const __half* __restrict__ A,
                                                const __half* __restrict__ B,
                                                __half* __restrict__ C) {
    extern __shared__ __align__(1024) char smem[];
    const int tid = threadIdx.x, lane = tid & 31, wid = tid >> 5;
    const int warp_m = wid & 1, warp_n = wid >> 1;       // 2 x 2, each 64x64
    const int rowBase = blockIdx.y * BM;
    const int colBase = blockIdx.x * BN;
    const uint32_t smemU = smem_u32(smem);
    const char* Ab = (const char*)A;
    const char* Bb = (const char*)B;

    float acc[4][8][4];
#pragma unroll
    for (int i = 0; i < 4; i++)
#pragma unroll
        for (int j = 0; j < 8; j++)
#pragma unroll
            for (int r = 0; r < 4; r++) acc[i][j][r] = 0.f;

    const int ldr = tid >> 3;            // 0..15
    const int ldc = tid & 7;             // 16B unit within 128B row

    auto load_stage = [&](int st, int ch) {
        uint32_t sa = smemU + st * STAGE_BYTES;
        uint32_t sb = sa + BM * 128;
#pragma unroll
        for (int i = 0; i < 8; i++) {
            int r = ldr + i * 16;
            uint32_t soff = (uint32_t)(r * 128 + ((ldc * 16) ^ ((r & 7) * 16)));
            CP_ASYNC16(sa + soff, Ab + (size_t)(rowBase + r) * (KS * 2) + ch * 128 + ldc * 16);
            CP_ASYNC16(sb + soff, Bb + (size_t)(colBase + r) * (KS * 2) + ch * 128 + ldc * 16);
        }
        CP_COMMIT();
    };

    load_stage(0, 0);
    load_stage(1, 1);

#pragma unroll
    for (int ch = 0; ch < 2; ch++) {               // K = 128 = 2 chunks of 64
        if (ch == 0) { CP_WAITG(1); } else { CP_WAITG(0); }
        __syncthreads();

        const uint32_t aB = smemU + ch * STAGE_BYTES;
        const uint32_t bB = aB + BM * 128;
#pragma unroll
        for (int s = 0; s < 4; s++) {
            uint32_t af[4][4], bf[8][2];
#pragma unroll
            for (int i = 0; i < 4; i++) {
                int row = warp_m * 64 + i * 16 + (lane & 15);
                int kb = s * 32 + ((lane >> 4) << 4);
                uint32_t addr = aB + row * 128 + (kb ^ ((row & 7) * 16));
                asm volatile("ldmatrix.sync.aligned.m8n8.x4.shared.b16 {%0,%1,%2,%3}, [%4];"
                             : "=r"(af[i][0]), "=r"(af[i][1]), "=r"(af[i][2]), "=r"(af[i][3])
                             : "r"(addr));
            }
            // B fragments: one x4 ldmatrix covers two adjacent n8 tiles
#pragma unroll
            for (int jp = 0; jp < 4; jp++) {
                int nrow = warp_n * 64 + (jp * 2 + (lane >> 4)) * 8 + (lane & 7);
                int kb = s * 32 + (((lane >> 3) & 1) << 4);
                uint32_t addr = bB + nrow * 128 + (kb ^ ((nrow & 7) * 16));
                asm volatile("ldmatrix.sync.aligned.m8n8.x4.shared.b16 {%0,%1,%2,%3}, [%4];"
                             : "=r"(bf[jp * 2][0]), "=r"(bf[jp * 2][1]),
                               "=r"(bf[jp * 2 + 1][0]), "=r"(bf[jp * 2 + 1][1])
                             : "r"(addr));
            }
#pragma unroll
            for (int i = 0; i < 4; i++)
#pragma unroll
                for (int j = 0; j < 8; j++)
                    asm volatile(
                        "mma.sync.aligned.m16n8k16.row.col.f32.f16.f16.f32 "
                        "{%0,%1,%2,%3}, {%4,%5,%6,%7}, {%8,%9}, {%0,%1,%2,%3};"
                        : "+f"(acc[i][j][0]), "+f"(acc[i][j][1]),
                          "+f"(acc[i][j][2]), "+f"(acc[i][j][3])
                        : "r"(af[i][0]), "r"(af[i][1]), "r"(af[i][2]), "r"(af[i][3]),
                          "r"(bf[j][0]), "r"(bf[j][1]));
        }
        if (ch == 0) __syncthreads();
    }

    // Epilogue: fp16 stores (half2), warp region 64x64
#pragma unroll
    for (int i = 0; i < 4; i++) {
        int r0 = rowBase + warp_m * 64 + i * 16 + (lane >> 2);
#pragma unroll
        for (int j = 0; j < 8; j++) {
            int col = colBase + warp_n * 64 + j * 8 + (lane & 3) * 2;
            *(__half2*)&C[(size_t)r0 * NCOLS + col] =
                __floats2half2_rn(acc[i][j][0], acc[i][j][1]);
            *(__half2*)&C[(size_t)(r0 + 8) * NCOLS + col] =
                __floats2half2_rn(acc[i][j][2], acc[i][j][3]);
        }
    }
}

// ---------------- edge message: ONE WARP PER EDGE, 16B loads ----------------
// Lanes 0-15 handle even k, lanes 16-31 odd k; each lane covers 8 contiguous cols.
// Partial sums combined via shfl_xor(16); lanes 0-15 issue the atomics.
__global__ void __launch_bounds__(256) edge_msg(const float* __restrict__ h,
                                                const __half* __restrict__ Y) {
    const int q = threadIdx.x >> 5;           // edge-within-block 0..7
    const int lane = threadIdx.x & 31;
    const int slot = blockIdx.x * 8 + q;
    const int eo  = g_perm[slot];             // broadcast load (same addr per warp)
    const int src = g_idx[eo];
    const int dst = g_idx[N_EDGES + eo];
    const float myh = h[eo * EH + lane];      // h[k] held by lane k
    const uint4* Y4 = (const uint4*)(Y + (size_t)src * NCOLS);  // 16B = 8 cols
    const int l16 = lane & 15;                // column-group 0..15 (8 cols each)
    const int p = lane >> 4;                  // k parity

    float m[8];
    if (p == 0) {                             // bias columns (cols 4096..4223): add once
        uint4 bv = Y4[512 + l16];
#pragma unroll
        for (int j = 0; j < 4; j++) {
            float2 f = __half22float2(((const __half2*)&bv)[j]);
            m[2 * j] = f.x; m[2 * j + 1] = f.y;
        }
    } else {
#pragma unroll
        for (int j = 0; j < 8; j++) m[j] = 0.f;
    }

#pragma unroll
    for (int t = 0; t < 16; t++) {
        const int k = 2 * t + p;
        uint4 v = Y4[k * 16 + l16];
        float hk = __shfl_sync(0xffffffffu, myh, k);
#pragma unroll
        for (int j = 0; j < 4; j++) {
            float2 f = __half22float2(((const __half2*)&v)[j]);
            m[2 * j]     = fmaf(hk, f.x, m[2 * j]);
            m[2 * j + 1] = fmaf(hk, f.y, m[2 * j + 1]);
        }
    }

#pragma unroll
    for (int j = 0; j < 8; j++) m[j] += __shfl_xor_sync(0xffffffffu, m[j], 16);

    if (p == 0) {
        float* d = &g_acc[dst * D + l16 * 8];
#pragma unroll
        for (int j = 0; j < 8; j++) atomicAdd(d + j, m[j]);
    }
}

// ---------------- combine (half2): out = Yroot + acc/max(cnt,1) + bias; resets acc ----------------
__global__ void combine(const __half* __restrict__ Y, const float* __restrict__ bias,
                        float* __restrict__ outf, __half* __restrict__ A3,
                        int do_relu) {
    int idx = blockIdx.x * blockDim.x + threadIdx.x;   // over N_NODES * 64 half2
    if (idx >= N_NODES * (D / 2)) return;
    int n = idx >> 6, o2 = idx & 63;
    float2 y = __half22float2(((const __half2*)Y)[(size_t)n * (NCOLS / 2) + (EH * D + D) / 2 + o2]);
    float2 a = ((float2*)g_acc)[idx];
    ((float2*)g_acc)[idx] = make_float2(0.f, 0.f);     // reset for next layer / replay
    float rc = 1.f / fmaxf(g_cnt[n], 1.f);
    float2 bv = ((const float2*)bias)[o2];
    float vx = fmaf(a.x, rc, y.x) + bv.x;
    float vy = fmaf(a.y, rc, y.y) + bv.y;
    if (do_relu) { vx = fmaxf(vx, 0.f); vy = fmaxf(vy, 0.f); }
    if (outf) ((float2*)outf)[idx] = make_float2(vx, vy);
    if (A3) ((__half2*)A3)[idx] = __floats2half2_rn(vx, vy);
}

// ---------------- launcher ----------------
extern "C" void kernel_launch(void* const* d_in, const int* in_sizes, int n_in,
                              void* d_out, int out_size) {
    const float* x       = (const float*)d_in[0];
    const void*  ei      = d_in[1];
    const float* ea      = (const float*)d_in[2];
    const float* w1_l1   = (const float*)d_in[3];
    const float* b1_l1   = (const float*)d_in[4];
    const float* w1_l2   = (const float*)d_in[5];
    const float* b1_l2   = (const float*)d_in[6];
    const float* w1_root = (const float*)d_in[7];
    const float* b1      = (const float*)d_in[8];
    const float* w2_l1   = (const float*)d_in[9];
    const float* b2_l1   = (const float*)d_in[10];
    const float* w2_l2   = (const float*)d_in[11];
    const float* b2_l2   = (const float*)d_in[12];
    const float* w2_root = (const float*)d_in[13];
    const float* b2      = (const float*)d_in[14];
    float*       out     = (float*)d_out;

    __half *Y, *A3, *B31, *B32;
    float *h1, *h2;
    cudaGetSymbolAddress((void**)&Y,   g_Y);
    cudaGetSymbolAddress((void**)&A3,  g_A3);
    cudaGetSymbolAddress((void**)&B31, g_B31);
    cudaGetSymbolAddress((void**)&B32, g_B32);
    cudaGetSymbolAddress((void**)&h1,  g_h1);
    cudaGetSymbolAddress((void**)&h2,  g_h2);

    const int SMEM_GEMM = 2 * STAGE_BYTES;              // 64 KB
    cudaFuncSetAttribute(gemm_mma, cudaFuncAttributeMaxDynamicSharedMemorySize, SMEM_GEMM);

    // ---- setup (indices+counts, scan, sort+edge MLP, weights) ----
    detect_zero<<<(N_NODES + 255) / 256, 256>>>((const long long*)ei);
    conv_count<<<(N_EDGES + 255) / 256, 256>>>(ei);
    scan_counts<<<1, 1024>>>();
    build_h2<<<(N_EDGES * EH + 255) / 256, 256>>>(ea, w1_l1, b1_l1, w2_l1, b2_l1, h1, h2);
    buildB2<<<(NCOLS * D + 255) / 256, 256>>>(w1_l2, b1_l2, w1_root,
                                              w2_l2, b2_l2, w2_root, B31, B32);

    dim3 gGemm(NCOLS / BN, N_NODES / BM);               // (34, 128)
    const int hgrid = (N_NODES * D / 2 + 255) / 256;    // half2-granular kernels
    const int egrid = N_EDGES / 8;

    // ---- layer 1 ----
    convA<<<hgrid, 256>>>(x, A3);
    gemm_mma<<<gGemm, 128, SMEM_GEMM>>>(A3, B31, Y);
    edge_msg<<<egrid, 256>>>(h1, Y);
    combine<<<hgrid, 256>>>(Y, b1, nullptr, A3, 1);
    // ---- layer 2 ----
    gemm_mma<<<gGemm, 128, SMEM_GEMM>>>(A3, B32, Y);
    edge_msg<<<egrid, 256>>>(h2, Y);
    combine<<<hgrid, 256>>>(Y, b2, nullptr, A3, 1);
    // ---- layer 3 ----
    gemm_mma<<<gGemm, 128, SMEM_GEMM>>>(A3, B32, Y);
    edge_msg<<<egrid, 256>>>(h2, Y);
    combine<<<hgrid, 256>>>(Y, b2, out, nullptr, 0);
}

// round 15
// speedup vs baseline: 1.0285x; 1.0285x over previous
#include <cuda_runtime.h>
#include <cuda_fp16.h>
#include <cstdint>

#define N_NODES 16384
#define N_EDGES 32768
#define D 128
#define EDGE_DIM 10
#define EH 32
#define NCOLS (EH * D + D + D)   // 4096 (L) + 128 (l2 bias) + 128 (root) = 4352
#define KS 128                   // fp16 single-term: A=hi, B=hi (K=128)
#define BM 128
#define BN 128
#define STAGE_BYTES (BM * 128 + BN * 128)   // 32 KB per stage

// ---------------- scratch (static device globals; no allocation) ----------------
__device__ __half g_Y[N_NODES * NCOLS];    // 142 MB (fp16 Y)
__device__ __half g_A3[N_NODES * KS];
__device__ __half g_B31[NCOLS * KS];
__device__ __half g_B32[NCOLS * KS];
__device__ float g_h1[N_EDGES * EH];
__device__ float g_h2[N_EDGES * EH];
__device__ float g_acc[N_NODES * D];       // zero-init; every combine restores zero
__device__ float g_cnt[N_NODES];
__device__ int   g_idx[2 * N_EDGES];
__device__ int   g_is64;
// edge sort-by-src
__device__ int g_srcCount[N_NODES];
__device__ int g_srcOff[N_NODES];
__device__ int g_rank[N_EDGES];
__device__ int g_perm[N_EDGES];

__device__ __forceinline__ uint32_t smem_u32(const void* p) {
    uint32_t a;
    asm("{ .reg .u64 t; cvta.to.shared.u64 t, %1; cvt.u32.u64 %0, t; }" : "=r"(a) : "l"(p));
    return a;
}
#define CP_ASYNC16(saddr, gptr) \
    asm volatile("cp.async.cg.shared.global [%0], [%1], 16;" :: "r"(saddr), "l"(gptr))
#define CP_COMMIT() asm volatile("cp.async.commit_group;" ::: "memory")
#define CP_WAITG(n) asm volatile("cp.async.wait_group %0;" :: "n"(n) : "memory")

// ---------------- edge_index dtype detection + zero counters ----------------
__global__ void detect_zero(const long long* __restrict__ ei) {
    int i = blockIdx.x * blockDim.x + threadIdx.x;
    if (i < N_NODES) { g_srcCount[i] = 0; g_cnt[i] = 0.f; }
    if (i == 0) {
        int ok = 1;
        for (int k = 0; k < 128; k++) {
            long long v = ei[k];
            if (v < 0 || v >= N_NODES) { ok = 0; break; }
        }
        g_is64 = ok;
    }
}

// ---------------- convert indices + count (fused) ----------------
__global__ void conv_count(const void* __restrict__ ei) {
    int e = blockIdx.x * blockDim.x + threadIdx.x;
    if (e >= N_EDGES) return;
    long long vs, vd;
    if (g_is64) {
        vs = ((const long long*)ei)[e];
        vd = ((const long long*)ei)[N_EDGES + e];
    } else {
        vs = ((const int*)ei)[e];
        vd = ((const int*)ei)[N_EDGES + e];
    }
    int s = (int)vs, d = (int)vd;
    s = s < 0 ? 0 : (s >= N_NODES ? N_NODES - 1 : s);
    d = d < 0 ? 0 : (d >= N_NODES ? N_NODES - 1 : d);
    g_idx[e] = s;
    g_idx[N_EDGES + e] = d;
    g_rank[e] = atomicAdd(&g_srcCount[s], 1);
    atomicAdd(&g_cnt[d], 1.0f);
}

__global__ void scan_counts() {          // 1 block, 1024 threads, 16 elems each
    __shared__ int part[1024];
    int t = threadIdx.x;
    int base = t * 16;
    int local[16];
    int s = 0;
#pragma unroll
    for (int i = 0; i < 16; i++) { local[i] = s; s += g_srcCount[base + i]; }
    part[t] = s;
    __syncthreads();
    for (int off = 1; off < 1024; off <<= 1) {
        int v = (t >= off) ? part[t - off] : 0;
        __syncthreads();
        part[t] += v;
        __syncthreads();
    }
    int pre = (t == 0) ? 0 : part[t - 1];
#pragma unroll
    for (int i = 0; i < 16; i++) g_srcOff[base + i] = pre + local[i];
}

// ---------------- h = relu(edge_attr @ l1w + l1b) both sets + place_edges (fused) ----------------
__global__ void build_h2(const float* __restrict__ ea,
                         const float* __restrict__ wA, const float* __restrict__ bA,
                         const float* __restrict__ wB, const float* __restrict__ bB,
                         float* __restrict__ hA, float* __restrict__ hB) {
    int idx = blockIdx.x * blockDim.x + threadIdx.x;
    if (idx >= N_EDGES * EH) return;
    int e = idx >> 5, j = idx & 31;
    if (j == 0) g_perm[g_srcOff[g_idx[e]] + g_rank[e]] = e;   // place edge in sorted order
    const float* ear = ea + e * EDGE_DIM;
    float sA = bA[j], sB = bB[j];
#pragma unroll
    for (int d = 0; d < EDGE_DIM; d++) {
        float v = ear[d];
        sA = fmaf(v, wA[d * EH + j], sA);
        sB = fmaf(v, wB[d * EH + j], sB);
    }
    hA[idx] = fmaxf(sA, 0.f);
    hB[idx] = fmaxf(sB, 0.f);
}

// ---------------- fp16 conversion of A (layer-1 input only), half2 ----------------
__global__ void convA(const float* __restrict__ X, __half* __restrict__ A3) {
    int idx = blockIdx.x * blockDim.x + threadIdx.x;
    if (idx >= N_NODES * D / 2) return;
    float2 v = ((const float2*)X)[idx];
    ((__half2*)A3)[idx] = __floats2half2_rn(v.x, v.y);
}

// ---------------- both B' matrices in one kernel ----------------
__global__ void buildB2(const float* __restrict__ l2wA, const float* __restrict__ bA,
                        const float* __restrict__ rootA,
                        const float* __restrict__ l2wB, const float* __restrict__ bB,
                        const float* __restrict__ rootB,
                        __half* __restrict__ B3A, __half* __restrict__ B3B) {
    int idx = blockIdx.x * blockDim.x + threadIdx.x;   // n*128 + k
    if (idx >= NCOLS * D) return;
    int n = idx >> 7, k = idx & 127;
    float vA, vB;
    if (n < EH * D) {
        int pos = (n >> 7) * (D * D) + k * D + (n & 127);
        vA = l2wA[pos]; vB = l2wB[pos];
    } else if (n < EH * D + D) {
        int pos = k * D + (n - EH * D);
        vA = bA[pos]; vB = bB[pos];
    } else {
        int pos = k * D + (n - EH * D - D);
        vA = rootA[pos]; vB = rootB[pos];
    }
    B3A[idx] = __float2half_rn(vA);
    B3B[idx] = __float2half_rn(vB);
}

// ---------------- HMMA GEMM: K=128 fully prefetched, CTA 128x128, 4 warps of 64x64 ----------------
__global__ void __launch_bounds__(128) gemm_mma(const __half* __restrict__ A,
                                                const __half* __restrict__ B,
                                                __half* __restrict__ C) {
    extern __shared__ __align__(1024) char smem[];
    const int tid = threadIdx.x, lane = tid & 31, wid = tid >> 5;
    const int warp_m = wid & 1, warp_n = wid >> 1;       // 2 x 2, each 64x64
    const int rowBase = blockIdx.y * BM;
    const int colBase = blockIdx.x * BN;
    const uint32_t smemU = smem_u32(smem);
    const char* Ab = (const char*)A;
    const char* Bb = (const char*)B;

    float acc[4][8][4];
#pragma unroll
    for (int i = 0; i < 4; i++)
#pragma unroll
        for (int j = 0; j < 8; j++)
#pragma unroll
            for (int r = 0; r < 4; r++) acc[i][j][r] = 0.f;

    const int ldr = tid >> 3;            // 0..15
    const int ldc = tid & 7;             // 16B unit within 128B row

    auto load_stage = [&](int st, int ch) {
        uint32_t sa = smemU + st * STAGE_BYTES;
        uint32_t sb = sa + BM * 128;
#pragma unroll
        for (int i = 0; i < 8; i++) {
            int r = ldr + i * 16;
            uint32_t soff = (uint32_t)(r * 128 + ((ldc * 16) ^ ((r & 7) * 16)));
            CP_ASYNC16(sa + soff, Ab + (size_t)(rowBase + r) * (KS * 2) + ch * 128 + ldc * 16);
            CP_ASYNC16(sb + soff, Bb + (size_t)(colBase + r) * (KS * 2) + ch * 128 + ldc * 16);
        }
        CP_COMMIT();
    };

    load_stage(0, 0);
    load_stage(1, 1);

#pragma unroll
    for (int ch = 0; ch < 2; ch++) {               // K = 128 = 2 chunks of 64
        if (ch == 0) { CP_WAITG(1); } else { CP_WAITG(0); }
        __syncthreads();

        const uint32_t aB = smemU + ch * STAGE_BYTES;
        const uint32_t bB = aB + BM * 128;
#pragma unroll
        for (int s = 0; s < 4; s++) {
            uint32_t af[4][4], bf[8][2];
#pragma unroll
            for (int i = 0; i < 4; i++) {
                int row = warp_m * 64 + i * 16 + (lane & 15);
                int kb = s * 32 + ((lane >> 4) << 4);
                uint32_t addr = aB + row * 128 + (kb ^ ((row & 7) * 16));
                asm volatile("ldmatrix.sync.aligned.m8n8.x4.shared.b16 {%0,%1,%2,%3}, [%4];"
                             : "=r"(af[i][0]), "=r"(af[i][1]), "=r"(af[i][2]), "=r"(af[i][3])
                             : "r"(addr));
            }
            // B fragments: one x4 ldmatrix covers two adjacent n8 tiles
#pragma unroll
            for (int jp = 0; jp < 4; jp++) {
                int nrow = warp_n * 64 + (jp * 2 + (lane >> 4)) * 8 + (lane & 7);
                int kb = s * 32 + (((lane >> 3) & 1) << 4);
                uint32_t addr = bB + nrow * 128 + (kb ^ ((nrow & 7) * 16));
                asm volatile("ldmatrix.sync.aligned.m8n8.x4.shared.b16 {%0,%1,%2,%3}, [%4];"
                             : "=r"(bf[jp * 2][0]), "=r"(bf[jp * 2][1]),
                               "=r"(bf[jp * 2 + 1][0]), "=r"(bf[jp * 2 + 1][1])
                             : "r"(addr));
            }
#pragma unroll
            for (int i = 0; i < 4; i++)
#pragma unroll
                for (int j = 0; j < 8; j++)
                    asm volatile(
                        "mma.sync.aligned.m16n8k16.row.col.f32.f16.f16.f32 "
                        "{%0,%1,%2,%3}, {%4,%5,%6,%7}, {%8,%9}, {%0,%1,%2,%3};"
                        : "+f"(acc[i][j][0]), "+f"(acc[i][j][1]),
                          "+f"(acc[i][j][2]), "+f"(acc[i][j][3])
                        : "r"(af[i][0]), "r"(af[i][1]), "r"(af[i][2]), "r"(af[i][3]),
                          "r"(bf[j][0]), "r"(bf[j][1]));
        }
        if (ch == 0) __syncthreads();
    }

    // Epilogue: fp16 stores (half2), warp region 64x64
#pragma unroll
    for (int i = 0; i < 4; i++) {
        int r0 = rowBase + warp_m * 64 + i * 16 + (lane >> 2);
#pragma unroll
        for (int j = 0; j < 8; j++) {
            int col = colBase + warp_n * 64 + j * 8 + (lane & 3) * 2;
            *(__half2*)&C[(size_t)r0 * NCOLS + col] =
                __floats2half2_rn(acc[i][j][0], acc[i][j][1]);
            *(__half2*)&C[(size_t)(r0 + 8) * NCOLS + col] =
                __floats2half2_rn(acc[i][j][2], acc[i][j][3]);
        }
    }
}

// ---------------- edge message (src-sorted flat, fp16 gather) + scatter-add ----------------
// R13 proven config: 4 edges per 256-thread block, 64 threads/edge, half2 columns.
__global__ void __launch_bounds__(256) edge_msg(const float* __restrict__ h,
                                                const __half* __restrict__ Y) {
    const int q = threadIdx.x >> 6;           // edge-within-block 0..3
    const int slot = blockIdx.x * 4 + q;
    const int o2 = threadIdx.x & 63;          // half2 column index
    __shared__ float sh[4][EH];
    __shared__ int se[4];
    if (o2 == 0) se[q] = g_perm[slot];
    __syncthreads();
    const int eo = se[q];
    if (o2 < EH) sh[q][o2] = h[eo * EH + o2];
    __syncthreads();
    const int src = g_idx[eo];
    const int dst = g_idx[N_EDGES + eo];
    const __half2* y2 = (const __half2*)(Y + (size_t)src * NCOLS);
    float2 b2 = __half22float2(y2[(EH * D) / 2 + o2]);    // l2-bias columns
    float mx = b2.x, my = b2.y;
#pragma unroll
    for (int k = 0; k < EH; k++) {
        float2 v = __half22float2(y2[k * 64 + o2]);
        float hk = sh[q][k];
        mx = fmaf(hk, v.x, mx);
        my = fmaf(hk, v.y, my);
    }
    atomicAdd(&g_acc[dst * D + 2 * o2], mx);
    atomicAdd(&g_acc[dst * D + 2 * o2 + 1], my);
}

// ---------------- combine (half2): out = Yroot + acc/max(cnt,1) + bias; resets acc ----------------
__global__ void combine(const __half* __restrict__ Y, const float* __restrict__ bias,
                        float* __restrict__ outf, __half* __restrict__ A3,
                        int do_relu) {
    int idx = blockIdx.x * blockDim.x + threadIdx.x;   // over N_NODES * 64 half2
    if (idx >= N_NODES * (D / 2)) return;
    int n = idx >> 6, o2 = idx & 63;
    float2 y = __half22float2(((const __half2*)Y)[(size_t)n * (NCOLS / 2) + (EH * D + D) / 2 + o2]);
    float2 a = ((float2*)g_acc)[idx];
    ((float2*)g_acc)[idx] = make_float2(0.f, 0.f);     // reset for next layer / replay
    float rc = 1.f / fmaxf(g_cnt[n], 1.f);
    float2 bv = ((const float2*)bias)[o2];
    float vx = fmaf(a.x, rc, y.x) + bv.x;
    float vy = fmaf(a.y, rc, y.y) + bv.y;
    if (do_relu) { vx = fmaxf(vx, 0.f); vy = fmaxf(vy, 0.f); }
    if (outf) ((float2*)outf)[idx] = make_float2(vx, vy);
    if (A3) ((__half2*)A3)[idx] = __floats2half2_rn(vx, vy);
}

// ---------------- launcher ----------------
extern "C" void kernel_launch(void* const* d_in, const int* in_sizes, int n_in,
                              void* d_out, int out_size) {
    const float* x       = (const float*)d_in[0];
    const void*  ei      = d_in[1];
    const float* ea      = (const float*)d_in[2];
    const float* w1_l1   = (const float*)d_in[3];
    const float* b1_l1   = (const float*)d_in[4];
    const float* w1_l2   = (const float*)d_in[5];
    const float* b1_l2   = (const float*)d_in[6];
    const float* w1_root = (const float*)d_in[7];
    const float* b1      = (const float*)d_in[8];
    const float* w2_l1   = (const float*)d_in[9];
    const float* b2_l1   = (const float*)d_in[10];
    const float* w2_l2   = (const float*)d_in[11];
    const float* b2_l2   = (const float*)d_in[12];
    const float* w2_root = (const float*)d_in[13];
    const float* b2      = (const float*)d_in[14];
    float*       out     = (float*)d_out;

    __half *Y, *A3, *B31, *B32;
    float *h1, *h2;
    cudaGetSymbolAddress((void**)&Y,   g_Y);
    cudaGetSymbolAddress((void**)&A3,  g_A3);
    cudaGetSymbolAddress((void**)&B31, g_B31);
    cudaGetSymbolAddress((void**)&B32, g_B32);
    cudaGetSymbolAddress((void**)&h1,  g_h1);
    cudaGetSymbolAddress((void**)&h2,  g_h2);

    const int SMEM_GEMM = 2 * STAGE_BYTES;              // 64 KB
    cudaFuncSetAttribute(gemm_mma, cudaFuncAttributeMaxDynamicSharedMemorySize, SMEM_GEMM);

    // ---- setup (indices+counts, scan, sort+edge MLP, weights) ----
    detect_zero<<<(N_NODES + 255) / 256, 256>>>((const long long*)ei);
    conv_count<<<(N_EDGES + 255) / 256, 256>>>(ei);
    scan_counts<<<1, 1024>>>();
    build_h2<<<(N_EDGES * EH + 255) / 256, 256>>>(ea, w1_l1, b1_l1, w2_l1, b2_l1, h1, h2);
    buildB2<<<(NCOLS * D + 255) / 256, 256>>>(w1_l2, b1_l2, w1_root,
                                              w2_l2, b2_l2, w2_root, B31, B32);

    dim3 gGemm(NCOLS / BN, N_NODES / BM);               // (34, 128)
    const int hgrid = (N_NODES * D / 2 + 255) / 256;    // half2-granular kernels
    const int egrid = N_EDGES / 4;

    // ---- layer 1 ----
    convA<<<hgrid, 256>>>(x, A3);
    gemm_mma<<<gGemm, 128, SMEM_GEMM>>>(A3, B31, Y);
    edge_msg<<<egrid, 256>>>(h1, Y);
    combine<<<hgrid, 256>>>(Y, b1, nullptr, A3, 1);
    // ---- layer 2 ----
    gemm_mma<<<gGemm, 128, SMEM_GEMM>>>(A3, B32, Y);
    edge_msg<<<egrid, 256>>>(h2, Y);
    combine<<<hgrid, 256>>>(Y, b2, nullptr, A3, 1);
    // ---- layer 3 ----
    gemm_mma<<<gGemm, 128, SMEM_GEMM>>>(A3, B32, Y);
    edge_msg<<<egrid, 256>>>(h2, Y);
    combine<<<hgrid, 256>>>(Y, b2, out, nullptr, 0);
}

// round 16
// speedup vs baseline: 1.1142x; 1.0833x over previous
#include <cuda_runtime.h>
#include <cuda_fp16.h>
#include <cstdint>

#define N_NODES 16384
#define N_EDGES 32768
#define D 128
#define EDGE_DIM 10
#define EH 32
#define NCOLS (EH * D + D + D)   // 4096 (L) + 128 (l2 bias) + 128 (root) = 4352
#define KS 128                   // fp16 single-term: A=hi, B=hi (K=128)
#define BM 128
#define BN 128
#define STAGE_BYTES (BM * 128 + BN * 128)   // 32 KB per stage

// ---------------- scratch (static device globals; no allocation) ----------------
__device__ __half g_Y[N_NODES * NCOLS];    // 142 MB (fp16 Y)
__device__ __half g_A3[N_NODES * KS];
__device__ __half g_B31[NCOLS * KS];
__device__ __half g_B32[NCOLS * KS];
__device__ float g_h1[N_EDGES * EH];
__device__ float g_h2[N_EDGES * EH];
__device__ float g_acc[N_NODES * D];       // zero-init; every combine restores zero
__device__ float g_cnt[N_NODES];
__device__ int   g_idx[2 * N_EDGES];
__device__ int   g_is64;
// edge sort-by-src
__device__ int g_srcCount[N_NODES];
__device__ int g_srcOff[N_NODES];
__device__ int g_rank[N_EDGES];
__device__ int g_perm[N_EDGES];

__device__ __forceinline__ uint32_t smem_u32(const void* p) {
    uint32_t a;
    asm("{ .reg .u64 t; cvta.to.shared.u64 t, %1; cvt.u32.u64 %0, t; }" : "=r"(a) : "l"(p));
    return a;
}
#define CP_ASYNC16(saddr, gptr) \
    asm volatile("cp.async.cg.shared.global [%0], [%1], 16;" :: "r"(saddr), "l"(gptr))
#define CP_COMMIT() asm volatile("cp.async.commit_group;" ::: "memory")
#define CP_WAITG(n) asm volatile("cp.async.wait_group %0;" :: "n"(n) : "memory")

// ---------------- edge_index dtype detection + zero counters ----------------
__global__ void detect_zero(const long long* __restrict__ ei) {
    int i = blockIdx.x * blockDim.x + threadIdx.x;
    if (i < N_NODES) { g_srcCount[i] = 0; g_cnt[i] = 0.f; }
    if (i == 0) {
        int ok = 1;
        for (int k = 0; k < 128; k++) {
            long long v = ei[k];
            if (v < 0 || v >= N_NODES) { ok = 0; break; }
        }
        g_is64 = ok;
    }
}

// ---------------- convert indices + count (fused) ----------------
__global__ void conv_count(const void* __restrict__ ei) {
    int e = blockIdx.x * blockDim.x + threadIdx.x;
    if (e >= N_EDGES) return;
    long long vs, vd;
    if (g_is64) {
        vs = ((const long long*)ei)[e];
        vd = ((const long long*)ei)[N_EDGES + e];
    } else {
        vs = ((const int*)ei)[e];
        vd = ((const int*)ei)[N_EDGES + e];
    }
    int s = (int)vs, d = (int)vd;
    s = s < 0 ? 0 : (s >= N_NODES ? N_NODES - 1 : s);
    d = d < 0 ? 0 : (d >= N_NODES ? N_NODES - 1 : d);
    g_idx[e] = s;
    g_idx[N_EDGES + e] = d;
    g_rank[e] = atomicAdd(&g_srcCount[s], 1);
    atomicAdd(&g_cnt[d], 1.0f);
}

__global__ void scan_counts() {          // 1 block, 1024 threads, 16 elems each
    __shared__ int part[1024];
    int t = threadIdx.x;
    int base = t * 16;
    int local[16];
    int s = 0;
#pragma unroll
    for (int i = 0; i < 16; i++) { local[i] = s; s += g_srcCount[base + i]; }
    part[t] = s;
    __syncthreads();
    for (int off = 1; off < 1024; off <<= 1) {
        int v = (t >= off) ? part[t - off] : 0;
        __syncthreads();
        part[t] += v;
        __syncthreads();
    }
    int pre = (t == 0) ? 0 : part[t - 1];
#pragma unroll
    for (int i = 0; i < 16; i++) g_srcOff[base + i] = pre + local[i];
}

// ---------------- h = relu(edge_attr @ l1w + l1b) both sets + place_edges (fused) ----------------
__global__ void build_h2(const float* __restrict__ ea,
                         const float* __restrict__ wA, const float* __restrict__ bA,
                         const float* __restrict__ wB, const float* __restrict__ bB,
                         float* __restrict__ hA, float* __restrict__ hB) {
    int idx = blockIdx.x * blockDim.x + threadIdx.x;
    if (idx >= N_EDGES * EH) return;
    int e = idx >> 5, j = idx & 31;
    if (j == 0) g_perm[g_srcOff[g_idx[e]] + g_rank[e]] = e;   // place edge in sorted order
    const float* ear = ea + e * EDGE_DIM;
    float sA = bA[j], sB = bB[j];
#pragma unroll
    for (int d = 0; d < EDGE_DIM; d++) {
        float v = ear[d];
        sA = fmaf(v, wA[d * EH + j], sA);
        sB = fmaf(v, wB[d * EH + j], sB);
    }
    hA[idx] = fmaxf(sA, 0.f);
    hB[idx] = fmaxf(sB, 0.f);
}

// ---------------- fp16 conversion of A (layer-1 input only) ----------------
__global__ void convA(const float* __restrict__ X, __half* __restrict__ A3) {
    int idx = blockIdx.x * blockDim.x + threadIdx.x;
    if (idx >= N_NODES * D) return;
    A3[idx] = __float2half_rn(X[idx]);
}

// ---------------- both B' matrices in one kernel ----------------
__global__ void buildB2(const float* __restrict__ l2wA, const float* __restrict__ bA,
                        const float* __restrict__ rootA,
                        const float* __restrict__ l2wB, const float* __restrict__ bB,
                        const float* __restrict__ rootB,
                        __half* __restrict__ B3A, __half* __restrict__ B3B) {
    int idx = blockIdx.x * blockDim.x + threadIdx.x;   // n*128 + k
    if (idx >= NCOLS * D) return;
    int n = idx >> 7, k = idx & 127;
    float vA, vB;
    if (n < EH * D) {
        int pos = (n >> 7) * (D * D) + k * D + (n & 127);
        vA = l2wA[pos]; vB = l2wB[pos];
    } else if (n < EH * D + D) {
        int pos = k * D + (n - EH * D);
        vA = bA[pos]; vB = bB[pos];
    } else {
        int pos = k * D + (n - EH * D - D);
        vA = rootA[pos]; vB = rootB[pos];
    }
    B3A[idx] = __float2half_rn(vA);
    B3B[idx] = __float2half_rn(vB);
}

// ---------------- HMMA GEMM: K=128 fully prefetched, CTA 128x128, 4 warps of 64x64 ----------------
__global__ void __launch_bounds__(128) gemm_mma(const __half* __restrict__ A,
                                                const __half* __restrict__ B,
                                                __half* __restrict__ C) {
    extern __shared__ __align__(1024) char smem[];
    const int tid = threadIdx.x, lane = tid & 31, wid = tid >> 5;
    const int warp_m = wid & 1, warp_n = wid >> 1;       // 2 x 2, each 64x64
    const int rowBase = blockIdx.y * BM;
    const int colBase = blockIdx.x * BN;
    const uint32_t smemU = smem_u32(smem);
    const char* Ab = (const char*)A;
    const char* Bb = (const char*)B;

    float acc[4][8][4];
#pragma unroll
    for (int i = 0; i < 4; i++)
#pragma unroll
        for (int j = 0; j < 8; j++)
#pragma unroll
            for (int r = 0; r < 4; r++) acc[i][j][r] = 0.f;

    const int ldr = tid >> 3;            // 0..15
    const int ldc = tid & 7;             // 16B unit within 128B row

    auto load_stage = [&](int st, int ch) {
        uint32_t sa = smemU + st * STAGE_BYTES;
        uint32_t sb = sa + BM * 128;
#pragma unroll
        for (int i = 0; i < 8; i++) {
            int r = ldr + i * 16;
            uint32_t soff = (uint32_t)(r * 128 + ((ldc * 16) ^ ((r & 7) * 16)));
            CP_ASYNC16(sa + soff, Ab + (size_t)(rowBase + r) * (KS * 2) + ch * 128 + ldc * 16);
            CP_ASYNC16(sb + soff, Bb + (size_t)(colBase + r) * (KS * 2) + ch * 128 + ldc * 16);
        }
        CP_COMMIT();
    };

    load_stage(0, 0);
    load_stage(1, 1);

#pragma unroll
    for (int ch = 0; ch < 2; ch++) {               // K = 128 = 2 chunks of 64
        if (ch == 0) { CP_WAITG(1); } else { CP_WAITG(0); }
        __syncthreads();

        const uint32_t aB = smemU + ch * STAGE_BYTES;
        const uint32_t bB = aB + BM * 128;
#pragma unroll
        for (int s = 0; s < 4; s++) {
            uint32_t af[4][4], bf[8][2];
#pragma unroll
            for (int i = 0; i < 4; i++) {
                int row = warp_m * 64 + i * 16 + (lane & 15);
                int kb = s * 32 + ((lane >> 4) << 4);
                uint32_t addr = aB + row * 128 + (kb ^ ((row & 7) * 16));
                asm volatile("ldmatrix.sync.aligned.m8n8.x4.shared.b16 {%0,%1,%2,%3}, [%4];"
                             : "=r"(af[i][0]), "=r"(af[i][1]), "=r"(af[i][2]), "=r"(af[i][3])
                             : "r"(addr));
            }
            // B fragments: one x4 ldmatrix covers two adjacent n8 tiles
#pragma unroll
            for (int jp = 0; jp < 4; jp++) {
                int nrow = warp_n * 64 + (jp * 2 + (lane >> 4)) * 8 + (lane & 7);
                int kb = s * 32 + (((lane >> 3) & 1) << 4);
                uint32_t addr = bB + nrow * 128 + (kb ^ ((nrow & 7) * 16));
                asm volatile("ldmatrix.sync.aligned.m8n8.x4.shared.b16 {%0,%1,%2,%3}, [%4];"
                             : "=r"(bf[jp * 2][0]), "=r"(bf[jp * 2][1]),
                               "=r"(bf[jp * 2 + 1][0]), "=r"(bf[jp * 2 + 1][1])
                             : "r"(addr));
            }
#pragma unroll
            for (int i = 0; i < 4; i++)
#pragma unroll
                for (int j = 0; j < 8; j++)
                    asm volatile(
                        "mma.sync.aligned.m16n8k16.row.col.f32.f16.f16.f32 "
                        "{%0,%1,%2,%3}, {%4,%5,%6,%7}, {%8,%9}, {%0,%1,%2,%3};"
                        : "+f"(acc[i][j][0]), "+f"(acc[i][j][1]),
                          "+f"(acc[i][j][2]), "+f"(acc[i][j][3])
                        : "r"(af[i][0]), "r"(af[i][1]), "r"(af[i][2]), "r"(af[i][3]),
                          "r"(bf[j][0]), "r"(bf[j][1]));
        }
        if (ch == 0) __syncthreads();
    }

    // Epilogue: fp16 stores (half2), warp region 64x64
#pragma unroll
    for (int i = 0; i < 4; i++) {
        int r0 = rowBase + warp_m * 64 + i * 16 + (lane >> 2);
#pragma unroll
        for (int j = 0; j < 8; j++) {
            int col = colBase + warp_n * 64 + j * 8 + (lane & 3) * 2;
            *(__half2*)&C[(size_t)r0 * NCOLS + col] =
                __floats2half2_rn(acc[i][j][0], acc[i][j][1]);
            *(__half2*)&C[(size_t)(r0 + 8) * NCOLS + col] =
                __floats2half2_rn(acc[i][j][2], acc[i][j][3]);
        }
    }
}

// ---------------- edge message: 4 edges/block, 64 threads/edge, 8B loads ----------------
// Warp 0 of each edge handles k=0..15 + bias row; warp 1 handles k=16..31.
// Each thread owns 4 contiguous cols (uint2 = 4 halfs); both warps atomically
// add their partial k-sums (no cross-warp reduction needed).
__global__ void __launch_bounds__(256) edge_msg(const float* __restrict__ h,
                                                const __half* __restrict__ Y) {
    const int q = threadIdx.x >> 6;           // edge-within-block 0..3
    const int t = threadIdx.x & 63;           // thread within edge
    const int w = t >> 5;                     // 0: k 0..15 (+bias), 1: k 16..31
    const int lane = t & 31;                  // col group (4 cols each)
    __shared__ float sh[4][EH];
    __shared__ int se[4];
    if (t == 0) se[q] = g_perm[blockIdx.x * 4 + q];
    __syncthreads();
    const int eo = se[q];
    if (t < EH) sh[q][t] = h[eo * EH + t];
    __syncthreads();
    const int src = g_idx[eo];
    const int dst = g_idx[N_EDGES + eo];
    const uint2* y4 = (const uint2*)(Y + (size_t)src * NCOLS);  // 8B = 4 cols

    float m0, m1, m2, m3;
    if (w == 0) {                             // bias row (cols 4096..4223), added once
        uint2 bv = y4[(EH * D) / 4 + lane];
        float2 f0 = __half22float2(*(const __half2*)&bv.x);
        float2 f1 = __half22float2(*(const __half2*)&bv.y);
        m0 = f0.x; m1 = f0.y; m2 = f1.x; m3 = f1.y;
    } else {
        m0 = m1 = m2 = m3 = 0.f;
    }

#pragma unroll
    for (int kk = 0; kk < 16; kk++) {
        const int k = w * 16 + kk;
        uint2 v = y4[k * 32 + lane];          // row k: 128 cols = 32 uint2
        float hk = sh[q][k];
        float2 f0 = __half22float2(*(const __half2*)&v.x);
        float2 f1 = __half22float2(*(const __half2*)&v.y);
        m0 = fmaf(hk, f0.x, m0);
        m1 = fmaf(hk, f0.y, m1);
        m2 = fmaf(hk, f1.x, m2);
        m3 = fmaf(hk, f1.y, m3);
    }

    float* d = &g_acc[dst * D + lane * 4];
    atomicAdd(d + 0, m0);
    atomicAdd(d + 1, m1);
    atomicAdd(d + 2, m2);
    atomicAdd(d + 3, m3);
}

// ---------------- combine: out = Yroot + acc/max(cnt,1) + bias; resets acc to 0 ----------------
__global__ void combine(const __half* __restrict__ Y, const float* __restrict__ bias,
                        float* __restrict__ outf, __half* __restrict__ A3,
                        int do_relu) {
    int idx = blockIdx.x * blockDim.x + threadIdx.x;
    if (idx >= N_NODES * D) return;
    int n = idx >> 7, o = idx & 127;
    float v = __half2float(Y[(size_t)n * NCOLS + EH * D + D + o])
            + g_acc[idx] / fmaxf(g_cnt[n], 1.f) + bias[o];
    g_acc[idx] = 0.f;                         // reset for next layer / next replay
    if (do_relu) v = fmaxf(v, 0.f);
    if (outf) outf[idx] = v;
    if (A3) A3[idx] = __float2half_rn(v);
}

// ---------------- launcher ----------------
extern "C" void kernel_launch(void* const* d_in, const int* in_sizes, int n_in,
                              void* d_out, int out_size) {
    const float* x       = (const float*)d_in[0];
    const void*  ei      = d_in[1];
    const float* ea      = (const float*)d_in[2];
    const float* w1_l1   = (const float*)d_in[3];
    const float* b1_l1   = (const float*)d_in[4];
    const float* w1_l2   = (const float*)d_in[5];
    const float* b1_l2   = (const float*)d_in[6];
    const float* w1_root = (const float*)d_in[7];
    const float* b1      = (const float*)d_in[8];
    const float* w2_l1   = (const float*)d_in[9];
    const float* b2_l1   = (const float*)d_in[10];
    const float* w2_l2   = (const float*)d_in[11];
    const float* b2_l2   = (const float*)d_in[12];
    const float* w2_root = (const float*)d_in[13];
    const float* b2      = (const float*)d_in[14];
    float*       out     = (float*)d_out;

    __half *Y, *A3, *B31, *B32;
    float *h1, *h2;
    cudaGetSymbolAddress((void**)&Y,   g_Y);
    cudaGetSymbolAddress((void**)&A3,  g_A3);
    cudaGetSymbolAddress((void**)&B31, g_B31);
    cudaGetSymbolAddress((void**)&B32, g_B32);
    cudaGetSymbolAddress((void**)&h1,  g_h1);
    cudaGetSymbolAddress((void**)&h2,  g_h2);

    const int SMEM_GEMM = 2 * STAGE_BYTES;              // 64 KB
    cudaFuncSetAttribute(gemm_mma, cudaFuncAttributeMaxDynamicSharedMemorySize, SMEM_GEMM);

    // ---- setup (indices+counts, scan, sort+edge MLP, weights) ----
    detect_zero<<<(N_NODES + 255) / 256, 256>>>((const long long*)ei);
    conv_count<<<(N_EDGES + 255) / 256, 256>>>(ei);
    scan_counts<<<1, 1024>>>();
    build_h2<<<(N_EDGES * EH + 255) / 256, 256>>>(ea, w1_l1, b1_l1, w2_l1, b2_l1, h1, h2);
    buildB2<<<(NCOLS * D + 255) / 256, 256>>>(w1_l2, b1_l2, w1_root,
                                              w2_l2, b2_l2, w2_root, B31, B32);

    dim3 gGemm(NCOLS / BN, N_NODES / BM);               // (34, 128)
    const int zgrid = (N_NODES * D + 255) / 256;
    const int egrid = N_EDGES / 4;

    // ---- layer 1 ----
    convA<<<zgrid, 256>>>(x, A3);
    gemm_mma<<<gGemm, 128, SMEM_GEMM>>>(A3, B31, Y);
    edge_msg<<<egrid, 256>>>(h1, Y);
    combine<<<zgrid, 256>>>(Y, b1, nullptr, A3, 1);
    // ---- layer 2 ----
    gemm_mma<<<gGemm, 128, SMEM_GEMM>>>(A3, B32, Y);
    edge_msg<<<egrid, 256>>>(h2, Y);
    combine<<<zgrid, 256>>>(Y, b2, nullptr, A3, 1);
    // ---- layer 3 ----
    gemm_mma<<<gGemm, 128, SMEM_GEMM>>>(A3, B32, Y);
    edge_msg<<<egrid, 256>>>(h2, Y);
    combine<<<zgrid, 256>>>(Y, b2, out, nullptr, 0);
}

// round 17
// speedup vs baseline: 1.1978x; 1.0751x over previous
#include <cuda_runtime.h>
#include <cuda_fp16.h>
#include <cstdint>

#define N_NODES 16384
#define N_EDGES 32768
#define D 128
#define EDGE_DIM 10
#define EH 32
#define NCOLS (EH * D + D + D)   // 4096 (L) + 128 (l2 bias) + 128 (root) = 4352
#define KS 128                   // fp16 single-term: A=hi, B=hi (K=128)
#define BM 128
#define BN 128
#define STAGE_BYTES (BM * 128 + BN * 128)   // 32 KB per stage

// ---------------- scratch (static device globals; no allocation) ----------------
__device__ __half g_Y[N_NODES * NCOLS];    // 142 MB (fp16 Y)
__device__ __half g_A3[N_NODES * KS];
__device__ __half g_B31[NCOLS * KS];
__device__ __half g_B32[NCOLS * KS];
__device__ float g_h1[N_EDGES * EH];
__device__ float g_h2[N_EDGES * EH];
__device__ float g_acc[N_NODES * D];       // zero-init; every combine restores zero
__device__ float g_cnt[N_NODES];
__device__ int   g_idx[2 * N_EDGES];
__device__ int   g_is64;
// edge sort-by-src
__device__ int g_srcCount[N_NODES];
__device__ int g_srcOff[N_NODES];
__device__ int g_rank[N_EDGES];
__device__ int g_perm[N_EDGES];

__device__ __forceinline__ uint32_t smem_u32(const void* p) {
    uint32_t a;
    asm("{ .reg .u64 t; cvta.to.shared.u64 t, %1; cvt.u32.u64 %0, t; }" : "=r"(a) : "l"(p));
    return a;
}
#define CP_ASYNC16(saddr, gptr) \
    asm volatile("cp.async.cg.shared.global [%0], [%1], 16;" :: "r"(saddr), "l"(gptr))
#define CP_COMMIT() asm volatile("cp.async.commit_group;" ::: "memory")
#define CP_WAITG(n) asm volatile("cp.async.wait_group %0;" :: "n"(n) : "memory")

// ---------------- edge_index dtype detection + zero counters ----------------
__global__ void detect_zero(const long long* __restrict__ ei) {
    int i = blockIdx.x * blockDim.x + threadIdx.x;
    if (i < N_NODES) { g_srcCount[i] = 0; g_cnt[i] = 0.f; }
    if (i == 0) {
        int ok = 1;
        for (int k = 0; k < 128; k++) {
            long long v = ei[k];
            if (v < 0 || v >= N_NODES) { ok = 0; break; }
        }
        g_is64 = ok;
    }
}

// ---------------- convert indices + count (fused) ----------------
__global__ void conv_count(const void* __restrict__ ei) {
    int e = blockIdx.x * blockDim.x + threadIdx.x;
    if (e >= N_EDGES) return;
    long long vs, vd;
    if (g_is64) {
        vs = ((const long long*)ei)[e];
        vd = ((const long long*)ei)[N_EDGES + e];
    } else {
        vs = ((const int*)ei)[e];
        vd = ((const int*)ei)[N_EDGES + e];
    }
    int s = (int)vs, d = (int)vd;
    s = s < 0 ? 0 : (s >= N_NODES ? N_NODES - 1 : s);
    d = d < 0 ? 0 : (d >= N_NODES ? N_NODES - 1 : d);
    g_idx[e] = s;
    g_idx[N_EDGES + e] = d;
    g_rank[e] = atomicAdd(&g_srcCount[s], 1);
    atomicAdd(&g_cnt[d], 1.0f);
}

__global__ void scan_counts() {          // 1 block, 1024 threads, 16 elems each
    __shared__ int part[1024];
    int t = threadIdx.x;
    int base = t * 16;
    int local[16];
    int s = 0;
#pragma unroll
    for (int i = 0; i < 16; i++) { local[i] = s; s += g_srcCount[base + i]; }
    part[t] = s;
    __syncthreads();
    for (int off = 1; off < 1024; off <<= 1) {
        int v = (t >= off) ? part[t - off] : 0;
        __syncthreads();
        part[t] += v;
        __syncthreads();
    }
    int pre = (t == 0) ? 0 : part[t - 1];
#pragma unroll
    for (int i = 0; i < 16; i++) g_srcOff[base + i] = pre + local[i];
}

// ---------------- h = relu(edge_attr @ l1w + l1b) both sets + place_edges (fused) ----------------
__global__ void build_h2(const float* __restrict__ ea,
                         const float* __restrict__ wA, const float* __restrict__ bA,
                         const float* __restrict__ wB, const float* __restrict__ bB,
                         float* __restrict__ hA, float* __restrict__ hB) {
    int idx = blockIdx.x * blockDim.x + threadIdx.x;
    if (idx >= N_EDGES * EH) return;
    int e = idx >> 5, j = idx & 31;
    if (j == 0) g_perm[g_srcOff[g_idx[e]] + g_rank[e]] = e;   // place edge in sorted order
    const float* ear = ea + e * EDGE_DIM;
    float sA = bA[j], sB = bB[j];
#pragma unroll
    for (int d = 0; d < EDGE_DIM; d++) {
        float v = ear[d];
        sA = fmaf(v, wA[d * EH + j], sA);
        sB = fmaf(v, wB[d * EH + j], sB);
    }
    hA[idx] = fmaxf(sA, 0.f);
    hB[idx] = fmaxf(sB, 0.f);
}

// ---------------- fp16 conversion of A (layer-1 input only) ----------------
__global__ void convA(const float* __restrict__ X, __half* __restrict__ A3) {
    int idx = blockIdx.x * blockDim.x + threadIdx.x;
    if (idx >= N_NODES * D) return;
    A3[idx] = __float2half_rn(X[idx]);
}

// ---------------- both B' matrices in one kernel ----------------
__global__ void buildB2(const float* __restrict__ l2wA, const float* __restrict__ bA,
                        const float* __restrict__ rootA,
                        const float* __restrict__ l2wB, const float* __restrict__ bB,
                        const float* __restrict__ rootB,
                        __half* __restrict__ B3A, __half* __restrict__ B3B) {
    int idx = blockIdx.x * blockDim.x + threadIdx.x;   // n*128 + k
    if (idx >= NCOLS * D) return;
    int n = idx >> 7, k = idx & 127;
    float vA, vB;
    if (n < EH * D) {
        int pos = (n >> 7) * (D * D) + k * D + (n & 127);
        vA = l2wA[pos]; vB = l2wB[pos];
    } else if (n < EH * D + D) {
        int pos = k * D + (n - EH * D);
        vA = bA[pos]; vB = bB[pos];
    } else {
        int pos = k * D + (n - EH * D - D);
        vA = rootA[pos]; vB = rootB[pos];
    }
    B3A[idx] = __float2half_rn(vA);
    B3B[idx] = __float2half_rn(vB);
}

// ---------------- HMMA GEMM: K=128 fully prefetched, CTA 128x128, 4 warps of 64x64 ----------------
__global__ void __launch_bounds__(128) gemm_mma(const __half* __restrict__ A,
                                                const __half* __restrict__ B,
                                                __half* __restrict__ C) {
    extern __shared__ __align__(1024) char smem[];
    const int tid = threadIdx.x, lane = tid & 31, wid = tid >> 5;
    const int warp_m = wid & 1, warp_n = wid >> 1;       // 2 x 2, each 64x64
    const int rowBase = blockIdx.y * BM;
    const int colBase = blockIdx.x * BN;
    const uint32_t smemU = smem_u32(smem);
    const char* Ab = (const char*)A;
    const char* Bb = (const char*)B;

    float acc[4][8][4];
#pragma unroll
    for (int i = 0; i < 4; i++)
#pragma unroll
        for (int j = 0; j < 8; j++)
#pragma unroll
            for (int r = 0; r < 4; r++) acc[i][j][r] = 0.f;

    const int ldr = tid >> 3;            // 0..15
    const int ldc = tid & 7;             // 16B unit within 128B row

    auto load_stage = [&](int st, int ch) {
        uint32_t sa = smemU + st * STAGE_BYTES;
        uint32_t sb = sa + BM * 128;
#pragma unroll
        for (int i = 0; i < 8; i++) {
            int r = ldr + i * 16;
            uint32_t soff = (uint32_t)(r * 128 + ((ldc * 16) ^ ((r & 7) * 16)));
            CP_ASYNC16(sa + soff, Ab + (size_t)(rowBase + r) * (KS * 2) + ch * 128 + ldc * 16);
            CP_ASYNC16(sb + soff, Bb + (size_t)(colBase + r) * (KS * 2) + ch * 128 + ldc * 16);
        }
        CP_COMMIT();
    };

    load_stage(0, 0);
    load_stage(1, 1);

#pragma unroll
    for (int ch = 0; ch < 2; ch++) {               // K = 128 = 2 chunks of 64
        if (ch == 0) { CP_WAITG(1); } else { CP_WAITG(0); }
        __syncthreads();

        const uint32_t aB = smemU + ch * STAGE_BYTES;
        const uint32_t bB = aB + BM * 128;
#pragma unroll
        for (int s = 0; s < 4; s++) {
            uint32_t af[4][4], bf[8][2];
#pragma unroll
            for (int i = 0; i < 4; i++) {
                int row = warp_m * 64 + i * 16 + (lane & 15);
                int kb = s * 32 + ((lane >> 4) << 4);
                uint32_t addr = aB + row * 128 + (kb ^ ((row & 7) * 16));
                asm volatile("ldmatrix.sync.aligned.m8n8.x4.shared.b16 {%0,%1,%2,%3}, [%4];"
                             : "=r"(af[i][0]), "=r"(af[i][1]), "=r"(af[i][2]), "=r"(af[i][3])
                             : "r"(addr));
            }
            // B fragments: one x4 ldmatrix covers two adjacent n8 tiles
#pragma unroll
            for (int jp = 0; jp < 4; jp++) {
                int nrow = warp_n * 64 + (jp * 2 + (lane >> 4)) * 8 + (lane & 7);
                int kb = s * 32 + (((lane >> 3) & 1) << 4);
                uint32_t addr = bB + nrow * 128 + (kb ^ ((nrow & 7) * 16));
                asm volatile("ldmatrix.sync.aligned.m8n8.x4.shared.b16 {%0,%1,%2,%3}, [%4];"
                             : "=r"(bf[jp * 2][0]), "=r"(bf[jp * 2][1]),
                               "=r"(bf[jp * 2 + 1][0]), "=r"(bf[jp * 2 + 1][1])
                             : "r"(addr));
            }
#pragma unroll
            for (int i = 0; i < 4; i++)
#pragma unroll
                for (int j = 0; j < 8; j++)
                    asm volatile(
                        "mma.sync.aligned.m16n8k16.row.col.f32.f16.f16.f32 "
                        "{%0,%1,%2,%3}, {%4,%5,%6,%7}, {%8,%9}, {%0,%1,%2,%3};"
                        : "+f"(acc[i][j][0]), "+f"(acc[i][j][1]),
                          "+f"(acc[i][j][2]), "+f"(acc[i][j][3])
                        : "r"(af[i][0]), "r"(af[i][1]), "r"(af[i][2]), "r"(af[i][3]),
                          "r"(bf[j][0]), "r"(bf[j][1]));
        }
        if (ch == 0) __syncthreads();
    }

    // Epilogue: fp16 stores (half2), warp region 64x64
#pragma unroll
    for (int i = 0; i < 4; i++) {
        int r0 = rowBase + warp_m * 64 + i * 16 + (lane >> 2);
#pragma unroll
        for (int j = 0; j < 8; j++) {
            int col = colBase + warp_n * 64 + j * 8 + (lane & 3) * 2;
            *(__half2*)&C[(size_t)r0 * NCOLS + col] =
                __floats2half2_rn(acc[i][j][0], acc[i][j][1]);
            *(__half2*)&C[(size_t)(r0 + 8) * NCOLS + col] =
                __floats2half2_rn(acc[i][j][2], acc[i][j][3]);
        }
    }
}

// ---------------- edge message (src-sorted flat, fp16 gather) + scatter-add ----------------
// R13 proven config: 4 edges per 256-thread block, 64 threads/edge, half2 columns.
__global__ void __launch_bounds__(256) edge_msg(const float* __restrict__ h,
                                                const __half* __restrict__ Y) {
    const int q = threadIdx.x >> 6;           // edge-within-block 0..3
    const int slot = blockIdx.x * 4 + q;
    const int o2 = threadIdx.x & 63;          // half2 column index
    __shared__ float sh[4][EH];
    __shared__ int se[4];
    if (o2 == 0) se[q] = g_perm[slot];
    __syncthreads();
    const int eo = se[q];
    if (o2 < EH) sh[q][o2] = h[eo * EH + o2];
    __syncthreads();
    const int src = g_idx[eo];
    const int dst = g_idx[N_EDGES + eo];
    const __half2* y2 = (const __half2*)(Y + (size_t)src * NCOLS);
    float2 b2 = __half22float2(y2[(EH * D) / 2 + o2]);    // l2-bias columns
    float mx = b2.x, my = b2.y;
#pragma unroll
    for (int k = 0; k < EH; k++) {
        float2 v = __half22float2(y2[k * 64 + o2]);
        float hk = sh[q][k];
        mx = fmaf(hk, v.x, mx);
        my = fmaf(hk, v.y, my);
    }
    atomicAdd(&g_acc[dst * D + 2 * o2], mx);
    atomicAdd(&g_acc[dst * D + 2 * o2 + 1], my);
}

// ---------------- combine: out = Yroot + acc/max(cnt,1) + bias; resets acc to 0 ----------------
__global__ void combine(const __half* __restrict__ Y, const float* __restrict__ bias,
                        float* __restrict__ outf, __half* __restrict__ A3,
                        int do_relu) {
    int idx = blockIdx.x * blockDim.x + threadIdx.x;
    if (idx >= N_NODES * D) return;
    int n = idx >> 7, o = idx & 127;
    float v = __half2float(Y[(size_t)n * NCOLS + EH * D + D + o])
            + g_acc[idx] / fmaxf(g_cnt[n], 1.f) + bias[o];
    g_acc[idx] = 0.f;                         // reset for next layer / next replay
    if (do_relu) v = fmaxf(v, 0.f);
    if (outf) outf[idx] = v;
    if (A3) A3[idx] = __float2half_rn(v);
}

// ---------------- launcher (fork/join: setup chain overlaps layer-1 GEMM) ----------------
extern "C" void kernel_launch(void* const* d_in, const int* in_sizes, int n_in,
                              void* d_out, int out_size) {
    const float* x       = (const float*)d_in[0];
    const void*  ei      = d_in[1];
    const float* ea      = (const float*)d_in[2];
    const float* w1_l1   = (const float*)d_in[3];
    const float* b1_l1   = (const float*)d_in[4];
    const float* w1_l2   = (const float*)d_in[5];
    const float* b1_l2   = (const float*)d_in[6];
    const float* w1_root = (const float*)d_in[7];
    const float* b1      = (const float*)d_in[8];
    const float* w2_l1   = (const float*)d_in[9];
    const float* b2_l1   = (const float*)d_in[10];
    const float* w2_l2   = (const float*)d_in[11];
    const float* b2_l2   = (const float*)d_in[12];
    const float* w2_root = (const float*)d_in[13];
    const float* b2      = (const float*)d_in[14];
    float*       out     = (float*)d_out;

    __half *Y, *A3, *B31, *B32;
    float *h1, *h2;
    cudaGetSymbolAddress((void**)&Y,   g_Y);
    cudaGetSymbolAddress((void**)&A3,  g_A3);
    cudaGetSymbolAddress((void**)&B31, g_B31);
    cudaGetSymbolAddress((void**)&B32, g_B32);
    cudaGetSymbolAddress((void**)&h1,  g_h1);
    cudaGetSymbolAddress((void**)&h2,  g_h2);

    const int SMEM_GEMM = 2 * STAGE_BYTES;              // 64 KB
    cudaFuncSetAttribute(gemm_mma, cudaFuncAttributeMaxDynamicSharedMemorySize, SMEM_GEMM);

    // One-time host objects (device work is identical on every call).
    static cudaStream_t s_aux = nullptr;
    static cudaEvent_t ev_fork = nullptr, ev_join = nullptr;
    if (s_aux == nullptr) {
        cudaStreamCreateWithFlags(&s_aux, cudaStreamNonBlocking);
        cudaEventCreateWithFlags(&ev_fork, cudaEventDisableTiming);
        cudaEventCreateWithFlags(&ev_join, cudaEventDisableTiming);
    }

    dim3 gGemm(NCOLS / BN, N_NODES / BM);               // (34, 128)
    const int zgrid = (N_NODES * D + 255) / 256;
    const int egrid = N_EDGES / 4;

    // ---- fork: aux branch runs the edge-setup chain ----
    cudaEventRecord(ev_fork, 0);
    cudaStreamWaitEvent(s_aux, ev_fork, 0);
    detect_zero<<<(N_NODES + 255) / 256, 256, 0, s_aux>>>((const long long*)ei);
    conv_count<<<(N_EDGES + 255) / 256, 256, 0, s_aux>>>(ei);
    scan_counts<<<1, 1024, 0, s_aux>>>();
    build_h2<<<(N_EDGES * EH + 255) / 256, 256, 0, s_aux>>>(ea, w1_l1, b1_l1, w2_l1, b2_l1, h1, h2);
    cudaEventRecord(ev_join, s_aux);

    // ---- main branch: weights + layer-1 GEMM (independent of edge setup) ----
    buildB2<<<(NCOLS * D + 255) / 256, 256>>>(w1_l2, b1_l2, w1_root,
                                              w2_l2, b2_l2, w2_root, B31, B32);
    convA<<<zgrid, 256>>>(x, A3);
    gemm_mma<<<gGemm, 128, SMEM_GEMM>>>(A3, B31, Y);

    // ---- join: edge_msg needs g_perm / g_idx / g_cnt / h ----
    cudaStreamWaitEvent(0, ev_join, 0);

    // ---- layer 1 ----
    edge_msg<<<egrid, 256>>>(h1, Y);
    combine<<<zgrid, 256>>>(Y, b1, nullptr, A3, 1);
    // ---- layer 2 ----
    gemm_mma<<<gGemm, 128, SMEM_GEMM>>>(A3, B32, Y);
    edge_msg<<<egrid, 256>>>(h2, Y);
    combine<<<zgrid, 256>>>(Y, b2, nullptr, A3, 1);
    // ---- layer 3 ----
    gemm_mma<<<gGemm, 128, SMEM_GEMM>>>(A3, B32, Y);
    edge_msg<<<egrid, 256>>>(h2, Y);
    combine<<<zgrid, 256>>>(Y, b2, out, nullptr, 0);
}